// round 1
// baseline (speedup 1.0000x reference)
#include <cuda_runtime.h>

#define HDIM   128
#define NSTEPS 60
#define SB     32      // samples per block
#define SPH    8       // f32x2 sample-pairs per thread-half
#define WPAD   129     // padded weight row (conflict-free fwd+transposed reads)
#define CPAD   18      // padded activation row (f32x2 units, keeps 16B align)

typedef unsigned long long u64;

// ---- f32x2 packed helpers (Blackwell packed fp32 pipe) ----
__device__ __forceinline__ u64 pack2(float a, float b) {
    u64 r; asm("mov.b64 %0, {%1, %2};" : "=l"(r) : "f"(a), "f"(b)); return r;
}
__device__ __forceinline__ float2 unpack2(u64 v) {
    float2 r; asm("mov.b64 {%0, %1}, %2;" : "=f"(r.x), "=f"(r.y) : "l"(v)); return r;
}
__device__ __forceinline__ u64 ffma2(u64 a, u64 b, u64 c) {
    u64 d; asm("fma.rn.f32x2 %0, %1, %2, %3;" : "=l"(d) : "l"(a), "l"(b), "l"(c)); return d;
}
__device__ __forceinline__ u64 fmul2(u64 a, u64 b) {
    u64 d; asm("mul.rn.f32x2 %0, %1, %2;" : "=l"(d) : "l"(a), "l"(b)); return d;
}
__device__ __forceinline__ u64 fadd2(u64 a, u64 b) {
    u64 d; asm("add.rn.f32x2 %0, %1, %2;" : "=l"(d) : "l"(a), "l"(b)); return d;
}

// silu + its derivative, 2 lanes at a time
__device__ __forceinline__ void silu2(u64 z, u64& h, u64& d) {
    float2 zf = unpack2(z);
    float e0 = __expf(-zf.x), e1 = __expf(-zf.y);
    float s0 = 1.0f / (1.0f + e0), s1 = 1.0f / (1.0f + e1);
    float h0 = zf.x * s0,          h1 = zf.y * s1;
    float d0 = fmaf(h0, 1.0f - s0, s0);
    float d1 = fmaf(h1, 1.0f - s1, s1);
    h = pack2(h0, h1);
    d = pack2(d0, d1);
}

// 128-deep accumulate: acc[sp] += sum_k w[k*WS] * cur[k][spb+sp]
// WS = WPAD -> forward (W[k][t]); WS = 1 -> backward transposed (W[t][j])
template <int WS>
__device__ __forceinline__ void accum128(const float* __restrict__ wbase,
                                         const u64 (*__restrict__ cur)[CPAD],
                                         int spb, u64 acc[SPH]) {
#pragma unroll 8
    for (int k = 0; k < HDIM; k++) {
        float w = wbase[k * WS];
        u64 wp = pack2(w, w);
        const ulonglong2* p = reinterpret_cast<const ulonglong2*>(&cur[k][spb]);
        ulonglong2 c0 = p[0], c1 = p[1], c2 = p[2], c3 = p[3];
        acc[0] = ffma2(c0.x, wp, acc[0]);
        acc[1] = ffma2(c0.y, wp, acc[1]);
        acc[2] = ffma2(c1.x, wp, acc[2]);
        acc[3] = ffma2(c1.y, wp, acc[3]);
        acc[4] = ffma2(c2.x, wp, acc[4]);
        acc[5] = ffma2(c2.y, wp, acc[5]);
        acc[6] = ffma2(c3.x, wp, acc[6]);
        acc[7] = ffma2(c3.y, wp, acc[7]);
    }
}

// SMEM layout (bytes):
//   cur  : [0, 18432)                 u64[128][18]
//   w2s  : [18432, 84480)             float[128*129]
//   w3s  : [84480, 150528)
//   w4s  : [150528, 216576)
//   w1s  : [216576, 217600)           float[256]
//   w5s  : [217600, 218112)           float[128]
//   b1s..b4s : [218112, 220160)       4 x float[128]
//   xs   : [220160, 220416)           u64[32]  (xs[d*16+sp])
#define SMEM_BYTES 220416

__global__ void __launch_bounds__(256, 1)
ebm_mcmc_kernel(const float* __restrict__ x0,
                const float* __restrict__ w1, const float* __restrict__ b1,
                const float* __restrict__ w2, const float* __restrict__ b2,
                const float* __restrict__ w3, const float* __restrict__ b3,
                const float* __restrict__ w4, const float* __restrict__ b4,
                const float* __restrict__ w5,
                const float* __restrict__ noise,
                float* __restrict__ out, int nsamp) {
    extern __shared__ unsigned char smraw[];
    u64 (*cur)[CPAD] = reinterpret_cast<u64(*)[CPAD]>(smraw);
    float* w2s = reinterpret_cast<float*>(smraw + 18432);
    float* w3s = w2s + HDIM * WPAD;
    float* w4s = w3s + HDIM * WPAD;
    float* w1s = w4s + HDIM * WPAD;   // [2][128]
    float* w5s = w1s + 256;
    float* b1s = w5s + 128;
    float* b2s = b1s + 128;
    float* b3s = b2s + 128;
    float* b4s = b3s + 128;
    u64*   xs  = reinterpret_cast<u64*>(b4s + 128);   // xs[d*16 + sp]

    const int tid = threadIdx.x;
    const int t   = tid & 127;        // owned feature column
    const int spb = (tid >> 7) * SPH; // first sample-pair of this half
    const int s0  = blockIdx.x * SB;

    // ---- load weights into SMEM (once per block, reused 60 steps) ----
    for (int idx = tid; idx < HDIM * HDIM; idx += 256) {
        int r = idx >> 7, c = idx & 127;
        int o = r * WPAD + c;
        w2s[o] = w2[idx];
        w3s[o] = w3[idx];
        w4s[o] = w4[idx];
    }
    w1s[tid] = w1[tid];
    if (tid < 128) {
        w5s[tid] = w5[tid];
        b1s[tid] = b1[tid];
        b2s[tid] = b2[tid];
        b3s[tid] = b3[tid];
        b4s[tid] = b4[tid];
    }
    if (tid < 32) {
        int d = tid & 1, sp = tid >> 1;
        size_t bx = (size_t)(s0 + 2 * sp) * 2 + d;
        xs[d * 16 + sp] = pack2(x0[bx], x0[bx + 2]);
    }
    __syncthreads();

    // silu' storage (registers): 4 layers x 8 pairs
    u64 s1[SPH], s2[SPH], s3[SPH], s4[SPH];

    const int part = tid & 7;
    const int spv  = (tid >> 3) & 15;
    const int dd   = tid >> 7;

    for (int i = 0; i < NSTEPS; i++) {
        float fi  = (float)i;
        float eps = 10.0f * (1.0f - fi / 60.0f);
        float cn  = sqrtf(2.0f * eps) * 0.005f;

        // prefetch this step's noise (consumed ~20k cycles later)
        float nz0 = 0.0f, nz1 = 0.0f;
        if (part == 0) {
            size_t base = ((size_t)i * nsamp + s0 + 2 * spv) * 2 + dd;
            nz0 = noise[base];
            nz1 = noise[base + 2];
        }

        // ---- forward L1: z1 = x @ W1 + b1 ----
        {
            float wa = w1s[t], wb = w1s[128 + t], bb = b1s[t];
            u64 wap = pack2(wa, wa), wbp = pack2(wb, wb), bbp = pack2(bb, bb);
#pragma unroll
            for (int sp = 0; sp < SPH; sp++) {
                u64 z = ffma2(xs[spb + sp], wap, ffma2(xs[16 + spb + sp], wbp, bbp));
                u64 hv, dv;
                silu2(z, hv, dv);
                s1[sp] = dv;
                cur[t][spb + sp] = hv;
            }
        }
        __syncthreads();

        // ---- forward L2 ----
        {
            u64 acc[SPH];
            float bb = b2s[t]; u64 bbp = pack2(bb, bb);
#pragma unroll
            for (int sp = 0; sp < SPH; sp++) acc[sp] = bbp;
            accum128<WPAD>(w2s + t, cur, spb, acc);
            __syncthreads();
#pragma unroll
            for (int sp = 0; sp < SPH; sp++) {
                u64 hv, dv;
                silu2(acc[sp], hv, dv);
                s2[sp] = dv;
                cur[t][spb + sp] = hv;
            }
        }
        __syncthreads();

        // ---- forward L3 ----
        {
            u64 acc[SPH];
            float bb = b3s[t]; u64 bbp = pack2(bb, bb);
#pragma unroll
            for (int sp = 0; sp < SPH; sp++) acc[sp] = bbp;
            accum128<WPAD>(w3s + t, cur, spb, acc);
            __syncthreads();
#pragma unroll
            for (int sp = 0; sp < SPH; sp++) {
                u64 hv, dv;
                silu2(acc[sp], hv, dv);
                s3[sp] = dv;
                cur[t][spb + sp] = hv;
            }
        }
        __syncthreads();

        // ---- forward L4 (h4 never needed; only silu'(z4)) ----
        {
            u64 acc[SPH];
            float bb = b4s[t]; u64 bbp = pack2(bb, bb);
#pragma unroll
            for (int sp = 0; sp < SPH; sp++) acc[sp] = bbp;
            accum128<WPAD>(w4s + t, cur, spb, acc);
#pragma unroll
            for (int sp = 0; sp < SPH; sp++) {
                u64 hv, dv;
                silu2(acc[sp], hv, dv);
                s4[sp] = dv;   // hv dead
            }
        }
        // ---- backward seed: dz4 = w5 (.) silu'(z4) ----
        {
            float wv = w5s[t]; u64 wvp = pack2(wv, wv);
            u64 dz[SPH];
#pragma unroll
            for (int sp = 0; sp < SPH; sp++) dz[sp] = fmul2(wvp, s4[sp]);
            __syncthreads();              // L4 acc reads of cur (h3) done
#pragma unroll
            for (int sp = 0; sp < SPH; sp++) cur[t][spb + sp] = dz[sp];
        }
        __syncthreads();

        // ---- backward through W4: dz3 = (dz4 @ W4^T) (.) silu'(z3) ----
        {
            u64 acc[SPH];
#pragma unroll
            for (int sp = 0; sp < SPH; sp++) acc[sp] = 0ULL;
            accum128<1>(w4s + t * WPAD, cur, spb, acc);
            __syncthreads();
#pragma unroll
            for (int sp = 0; sp < SPH; sp++) cur[t][spb + sp] = fmul2(acc[sp], s3[sp]);
        }
        __syncthreads();

        // ---- backward through W3 -> dz2 ----
        {
            u64 acc[SPH];
#pragma unroll
            for (int sp = 0; sp < SPH; sp++) acc[sp] = 0ULL;
            accum128<1>(w3s + t * WPAD, cur, spb, acc);
            __syncthreads();
#pragma unroll
            for (int sp = 0; sp < SPH; sp++) cur[t][spb + sp] = fmul2(acc[sp], s2[sp]);
        }
        __syncthreads();

        // ---- backward through W2 -> dz1 ----
        {
            u64 acc[SPH];
#pragma unroll
            for (int sp = 0; sp < SPH; sp++) acc[sp] = 0ULL;
            accum128<1>(w2s + t * WPAD, cur, spb, acc);
            __syncthreads();
#pragma unroll
            for (int sp = 0; sp < SPH; sp++) cur[t][spb + sp] = fmul2(acc[sp], s1[sp]);
        }
        __syncthreads();

        // ---- g = dz1 @ W1^T, clip, Langevin update ----
        {
            u64 gacc = 0ULL;
            const float* wrow = w1s + dd * 128 + part * 16;
#pragma unroll
            for (int jj = 0; jj < 16; jj++) {
                float w = wrow[jj];
                gacc = ffma2(cur[part * 16 + jj][spv], pack2(w, w), gacc);
            }
            gacc = fadd2(gacc, __shfl_down_sync(0xffffffffu, gacc, 4, 8));
            gacc = fadd2(gacc, __shfl_down_sync(0xffffffffu, gacc, 2, 8));
            gacc = fadd2(gacc, __shfl_down_sync(0xffffffffu, gacc, 1, 8));
            if (part == 0) {
                float2 g = unpack2(gacc);
                g.x = fminf(fmaxf(g.x, -0.03f), 0.03f);
                g.y = fminf(fmaxf(g.y, -0.03f), 0.03f);
                float2 xv = unpack2(xs[dd * 16 + spv]);
                float ax = xv.x + cn * nz0;  ax += eps * g.x;
                float ay = xv.y + cn * nz1;  ay += eps * g.y;
                ax = fminf(fmaxf(ax, -2.43f), 3.05f);
                ay = fminf(fmaxf(ay, -2.43f), 3.05f);
                xs[dd * 16 + spv] = pack2(ax, ay);
            }
        }
        __syncthreads();
    }

    // ---- write final x ----
    if (tid < 64) {
        int sl = tid >> 1, d = tid & 1;
        float2 v = unpack2(xs[d * 16 + (sl >> 1)]);
        out[(size_t)(s0 + sl) * 2 + d] = (sl & 1) ? v.y : v.x;
    }
}

extern "C" void kernel_launch(void* const* d_in, const int* in_sizes, int n_in,
                              void* d_out, int out_size) {
    const float* x0    = (const float*)d_in[0];
    const float* w1    = (const float*)d_in[1];
    const float* b1    = (const float*)d_in[2];
    const float* w2    = (const float*)d_in[3];
    const float* b2    = (const float*)d_in[4];
    const float* w3    = (const float*)d_in[5];
    const float* b3    = (const float*)d_in[6];
    const float* w4    = (const float*)d_in[7];
    const float* b4    = (const float*)d_in[8];
    const float* w5    = (const float*)d_in[9];
    const float* noise = (const float*)d_in[11];
    float* out = (float*)d_out;

    int nsamp = in_sizes[0] / 2;
    cudaFuncSetAttribute(ebm_mcmc_kernel,
                         cudaFuncAttributeMaxDynamicSharedMemorySize, SMEM_BYTES);
    int nblocks = nsamp / SB;
    ebm_mcmc_kernel<<<nblocks, 256, SMEM_BYTES>>>(
        x0, w1, b1, w2, b2, w3, b3, w4, b4, w5, noise, out, nsamp);
}

// round 4
// speedup vs baseline: 1.3064x; 1.3064x over previous
#include <cuda_runtime.h>

#define HDIM   128
#define NSTEPS 60
#define SB     32      // samples per block
#define WPAD   132     // padded weight row in floats (16B-aligned float4 rows)
#define CPAD   18      // activation row in f32x2 units (16B-aligned pairs)

typedef unsigned long long u64;

// ---- f32x2 packed helpers (Blackwell packed fp32 pipe) ----
__device__ __forceinline__ u64 pack2(float a, float b) {
    u64 r; asm("mov.b64 %0, {%1, %2};" : "=l"(r) : "f"(a), "f"(b)); return r;
}
__device__ __forceinline__ float2 unpack2(u64 v) {
    float2 r; asm("mov.b64 {%0, %1}, %2;" : "=f"(r.x), "=f"(r.y) : "l"(v)); return r;
}
__device__ __forceinline__ u64 ffma2(u64 a, u64 b, u64 c) {
    u64 d; asm("fma.rn.f32x2 %0, %1, %2, %3;" : "=l"(d) : "l"(a), "l"(b), "l"(c)); return d;
}
__device__ __forceinline__ u64 fmul2(u64 a, u64 b) {
    u64 d; asm("mul.rn.f32x2 %0, %1, %2;" : "=l"(d) : "l"(a), "l"(b)); return d;
}
__device__ __forceinline__ u64 fadd2(u64 a, u64 b) {
    u64 d; asm("add.rn.f32x2 %0, %1, %2;" : "=l"(d) : "l"(a), "l"(b)); return d;
}

// silu + derivative, 2 lanes at a time
__device__ __forceinline__ void silu2(u64 z, u64& h, u64& d) {
    float2 zf = unpack2(z);
    float e0 = __expf(-zf.x), e1 = __expf(-zf.y);
    float s0 = 1.0f / (1.0f + e0), s1 = 1.0f / (1.0f + e1);
    float h0 = zf.x * s0,          h1 = zf.y * s1;
    float d0 = fmaf(h0, 1.0f - s0, s0);
    float d1 = fmaf(h1, 1.0f - s1, s1);
    h = pack2(h0, h1);
    d = pack2(d0, d1);
}

// FORWARD register-tiled accumulate:
// acc[2*ff+pp] += sum_k W[k][f0+ff] * cur[k][p0+pp]
// ws = weight base + f0 (row stride WPAD)
__device__ __forceinline__ void accum_tile(const float* __restrict__ ws,
                                           const u64 (*__restrict__ cur)[CPAD],
                                           int p0, u64 acc[8]) {
#pragma unroll 8
    for (int k = 0; k < HDIM; k++) {
        float4 w = *reinterpret_cast<const float4*>(ws + k * WPAD);
        ulonglong2 h = *reinterpret_cast<const ulonglong2*>(&cur[k][p0]);
        u64 wa = pack2(w.x, w.x), wb = pack2(w.y, w.y);
        u64 wc = pack2(w.z, w.z), wd = pack2(w.w, w.w);
        acc[0] = ffma2(h.x, wa, acc[0]);  acc[1] = ffma2(h.y, wa, acc[1]);
        acc[2] = ffma2(h.x, wb, acc[2]);  acc[3] = ffma2(h.y, wb, acc[3]);
        acc[4] = ffma2(h.x, wc, acc[4]);  acc[5] = ffma2(h.y, wc, acc[5]);
        acc[6] = ffma2(h.x, wd, acc[6]);  acc[7] = ffma2(h.y, wd, acc[7]);
    }
}

// BACKWARD (transposed) register-tiled accumulate:
// acc[2*ff+pp] += sum_k W[f0+ff][k] * cur[k][p0+pp]
// ws = weight base + f0*WPAD. k processed 4 at a time with float4 row reads.
__device__ __forceinline__ void accum_tile_T(const float* __restrict__ ws,
                                             const u64 (*__restrict__ cur)[CPAD],
                                             int p0, u64 acc[8]) {
#pragma unroll 4
    for (int k = 0; k < HDIM; k += 4) {
        float4 w0 = *reinterpret_cast<const float4*>(ws + 0 * WPAD + k);
        float4 w1 = *reinterpret_cast<const float4*>(ws + 1 * WPAD + k);
        float4 w2 = *reinterpret_cast<const float4*>(ws + 2 * WPAD + k);
        float4 w3 = *reinterpret_cast<const float4*>(ws + 3 * WPAD + k);
        ulonglong2 h0 = *reinterpret_cast<const ulonglong2*>(&cur[k + 0][p0]);
        ulonglong2 h1 = *reinterpret_cast<const ulonglong2*>(&cur[k + 1][p0]);
        ulonglong2 h2 = *reinterpret_cast<const ulonglong2*>(&cur[k + 2][p0]);
        ulonglong2 h3 = *reinterpret_cast<const ulonglong2*>(&cur[k + 3][p0]);

        acc[0] = ffma2(h0.x, pack2(w0.x, w0.x), acc[0]);
        acc[1] = ffma2(h0.y, pack2(w0.x, w0.x), acc[1]);
        acc[0] = ffma2(h1.x, pack2(w0.y, w0.y), acc[0]);
        acc[1] = ffma2(h1.y, pack2(w0.y, w0.y), acc[1]);
        acc[0] = ffma2(h2.x, pack2(w0.z, w0.z), acc[0]);
        acc[1] = ffma2(h2.y, pack2(w0.z, w0.z), acc[1]);
        acc[0] = ffma2(h3.x, pack2(w0.w, w0.w), acc[0]);
        acc[1] = ffma2(h3.y, pack2(w0.w, w0.w), acc[1]);

        acc[2] = ffma2(h0.x, pack2(w1.x, w1.x), acc[2]);
        acc[3] = ffma2(h0.y, pack2(w1.x, w1.x), acc[3]);
        acc[2] = ffma2(h1.x, pack2(w1.y, w1.y), acc[2]);
        acc[3] = ffma2(h1.y, pack2(w1.y, w1.y), acc[3]);
        acc[2] = ffma2(h2.x, pack2(w1.z, w1.z), acc[2]);
        acc[3] = ffma2(h2.y, pack2(w1.z, w1.z), acc[3]);
        acc[2] = ffma2(h3.x, pack2(w1.w, w1.w), acc[2]);
        acc[3] = ffma2(h3.y, pack2(w1.w, w1.w), acc[3]);

        acc[4] = ffma2(h0.x, pack2(w2.x, w2.x), acc[4]);
        acc[5] = ffma2(h0.y, pack2(w2.x, w2.x), acc[5]);
        acc[4] = ffma2(h1.x, pack2(w2.y, w2.y), acc[4]);
        acc[5] = ffma2(h1.y, pack2(w2.y, w2.y), acc[5]);
        acc[4] = ffma2(h2.x, pack2(w2.z, w2.z), acc[4]);
        acc[5] = ffma2(h2.y, pack2(w2.z, w2.z), acc[5]);
        acc[4] = ffma2(h3.x, pack2(w2.w, w2.w), acc[4]);
        acc[5] = ffma2(h3.y, pack2(w2.w, w2.w), acc[5]);

        acc[6] = ffma2(h0.x, pack2(w3.x, w3.x), acc[6]);
        acc[7] = ffma2(h0.y, pack2(w3.x, w3.x), acc[7]);
        acc[6] = ffma2(h1.x, pack2(w3.y, w3.y), acc[6]);
        acc[7] = ffma2(h1.y, pack2(w3.y, w3.y), acc[7]);
        acc[6] = ffma2(h2.x, pack2(w3.z, w3.z), acc[6]);
        acc[7] = ffma2(h2.y, pack2(w3.z, w3.z), acc[7]);
        acc[6] = ffma2(h3.x, pack2(w3.w, w3.w), acc[6]);
        acc[7] = ffma2(h3.y, pack2(w3.w, w3.w), acc[7]);
    }
}

// SMEM layout (bytes):
//   cur  : [0, 18432)                   u64[128][18]
//   w2s  : 18432   float[128*132] = 67584 B
//   w3s  : 86016
//   w4s  : 153600
//   w1s  : 221184  float[2][128]
//   w5s  : 222208  float[128]
//   b1s..b4s : 222720..224768
//   xs   : 224768  u64[32]   (xs[d*16+p])
#define SMEM_BYTES 225024

__global__ void __launch_bounds__(256, 1)
ebm_mcmc_kernel(const float* __restrict__ x0,
                const float* __restrict__ w1, const float* __restrict__ b1,
                const float* __restrict__ w2, const float* __restrict__ b2,
                const float* __restrict__ w3, const float* __restrict__ b3,
                const float* __restrict__ w4, const float* __restrict__ b4,
                const float* __restrict__ w5,
                const float* __restrict__ noise,
                float* __restrict__ out, int nsamp) {
    extern __shared__ unsigned char smraw[];
    u64 (*cur)[CPAD] = reinterpret_cast<u64(*)[CPAD]>(smraw);
    float* w2s = reinterpret_cast<float*>(smraw + 18432);
    float* w3s = w2s + HDIM * WPAD;
    float* w4s = w3s + HDIM * WPAD;
    float* w1s = w4s + HDIM * WPAD;   // [2][128]
    float* w5s = w1s + 256;
    float* b1s = w5s + 128;
    float* b2s = b1s + 128;
    float* b3s = b2s + 128;
    float* b4s = b3s + 128;
    u64*   xs  = reinterpret_cast<u64*>(b4s + 128);   // xs[d*16 + p]

    const int tid = threadIdx.x;
    const int f0  = (tid >> 3) * 4;   // 4 contiguous output features
    const int p0  = (tid & 7) * 2;    // 2 contiguous sample-pairs
    const int s0  = blockIdx.x * SB;

    // ---- load weights into SMEM (once, reused 60 steps) ----
    for (int idx = tid; idx < HDIM * HDIM; idx += 256) {
        int r = idx >> 7, c = idx & 127;
        int o = r * WPAD + c;
        w2s[o] = w2[idx];
        w3s[o] = w3[idx];
        w4s[o] = w4[idx];
    }
    w1s[tid] = w1[tid];
    if (tid < 128) {
        w5s[tid] = w5[tid];
        b1s[tid] = b1[tid];
        b2s[tid] = b2[tid];
        b3s[tid] = b3[tid];
        b4s[tid] = b4[tid];
    }
    if (tid < 32) {
        int d = tid & 1, sp = tid >> 1;
        size_t bx = (size_t)(s0 + 2 * sp) * 2 + d;
        xs[d * 16 + sp] = pack2(x0[bx], x0[bx + 2]);
    }
    __syncthreads();

    // silu' storage: layers 1-3 persist across backward; layer 4 used immediately
    u64 sd1[8], sd2[8], sd3[8];

    const int part = tid & 7;
    const int spv  = (tid >> 3) & 15;
    const int dd   = tid >> 7;

    for (int i = 0; i < NSTEPS; i++) {
        float fi  = (float)i;
        float eps = 10.0f * (1.0f - fi / 60.0f);
        float cn  = sqrtf(2.0f * eps) * 0.005f;

        // prefetch this step's noise (consumed at step end)
        float nz0 = 0.0f, nz1 = 0.0f;
        if (part == 0) {
            size_t base = ((size_t)i * nsamp + s0 + 2 * spv) * 2 + dd;
            nz0 = noise[base];
            nz1 = noise[base + 2];
        }

        // ---- forward L1: z1 = x @ W1 + b1 ----
        {
            float4 wa = *reinterpret_cast<const float4*>(w1s + f0);
            float4 wb = *reinterpret_cast<const float4*>(w1s + 128 + f0);
            float4 bb = *reinterpret_cast<const float4*>(b1s + f0);
            u64 xa0 = xs[p0], xa1 = xs[p0 + 1];
            u64 xb0 = xs[16 + p0], xb1 = xs[16 + p0 + 1];
            float wav[4] = {wa.x, wa.y, wa.z, wa.w};
            float wbv[4] = {wb.x, wb.y, wb.z, wb.w};
            float bbv[4] = {bb.x, bb.y, bb.z, bb.w};
#pragma unroll
            for (int ff = 0; ff < 4; ff++) {
                u64 wap = pack2(wav[ff], wav[ff]);
                u64 wbp = pack2(wbv[ff], wbv[ff]);
                u64 bbp = pack2(bbv[ff], bbv[ff]);
                u64 z0 = ffma2(xa0, wap, ffma2(xb0, wbp, bbp));
                u64 z1 = ffma2(xa1, wap, ffma2(xb1, wbp, bbp));
                u64 h0, d0, h1, d1;
                silu2(z0, h0, d0);  silu2(z1, h1, d1);
                sd1[2 * ff] = d0;  sd1[2 * ff + 1] = d1;
                ulonglong2 st; st.x = h0; st.y = h1;
                *reinterpret_cast<ulonglong2*>(&cur[f0 + ff][p0]) = st;
            }
        }
        __syncthreads();

        // ---- forward L2 ----
        {
            u64 acc[8];
            float4 bb = *reinterpret_cast<const float4*>(b2s + f0);
            acc[0] = acc[1] = pack2(bb.x, bb.x);
            acc[2] = acc[3] = pack2(bb.y, bb.y);
            acc[4] = acc[5] = pack2(bb.z, bb.z);
            acc[6] = acc[7] = pack2(bb.w, bb.w);
            accum_tile(w2s + f0, cur, p0, acc);
            __syncthreads();
#pragma unroll
            for (int ff = 0; ff < 4; ff++) {
                u64 h0, d0, h1, d1;
                silu2(acc[2 * ff], h0, d0);  silu2(acc[2 * ff + 1], h1, d1);
                sd2[2 * ff] = d0;  sd2[2 * ff + 1] = d1;
                ulonglong2 st; st.x = h0; st.y = h1;
                *reinterpret_cast<ulonglong2*>(&cur[f0 + ff][p0]) = st;
            }
        }
        __syncthreads();

        // ---- forward L3 ----
        {
            u64 acc[8];
            float4 bb = *reinterpret_cast<const float4*>(b3s + f0);
            acc[0] = acc[1] = pack2(bb.x, bb.x);
            acc[2] = acc[3] = pack2(bb.y, bb.y);
            acc[4] = acc[5] = pack2(bb.z, bb.z);
            acc[6] = acc[7] = pack2(bb.w, bb.w);
            accum_tile(w3s + f0, cur, p0, acc);
            __syncthreads();
#pragma unroll
            for (int ff = 0; ff < 4; ff++) {
                u64 h0, d0, h1, d1;
                silu2(acc[2 * ff], h0, d0);  silu2(acc[2 * ff + 1], h1, d1);
                sd3[2 * ff] = d0;  sd3[2 * ff + 1] = d1;
                ulonglong2 st; st.x = h0; st.y = h1;
                *reinterpret_cast<ulonglong2*>(&cur[f0 + ff][p0]) = st;
            }
        }
        __syncthreads();

        // ---- forward L4 (h4 dead; only silu'(z4)) + backward seed dz4 = w5 .* silu'(z4) ----
        {
            u64 acc[8];
            float4 bb = *reinterpret_cast<const float4*>(b4s + f0);
            acc[0] = acc[1] = pack2(bb.x, bb.x);
            acc[2] = acc[3] = pack2(bb.y, bb.y);
            acc[4] = acc[5] = pack2(bb.z, bb.z);
            acc[6] = acc[7] = pack2(bb.w, bb.w);
            accum_tile(w4s + f0, cur, p0, acc);
            float4 w5v = *reinterpret_cast<const float4*>(w5s + f0);
            float w5a[4] = {w5v.x, w5v.y, w5v.z, w5v.w};
            u64 dz[8];
#pragma unroll
            for (int ff = 0; ff < 4; ff++) {
                u64 h0, d0, h1, d1;
                silu2(acc[2 * ff], h0, d0);  silu2(acc[2 * ff + 1], h1, d1);
                u64 wp = pack2(w5a[ff], w5a[ff]);
                dz[2 * ff]     = fmul2(wp, d0);
                dz[2 * ff + 1] = fmul2(wp, d1);
            }
            __syncthreads();   // everyone done reading h3 from cur
#pragma unroll
            for (int ff = 0; ff < 4; ff++) {
                ulonglong2 st; st.x = dz[2 * ff]; st.y = dz[2 * ff + 1];
                *reinterpret_cast<ulonglong2*>(&cur[f0 + ff][p0]) = st;
            }
        }
        __syncthreads();

        // ---- backward through W4: dz3[j] = (sum_t dz4[t] * W4[j][t]) .* silu'(z3) ----
        {
            u64 acc[8];
#pragma unroll
            for (int q = 0; q < 8; q++) acc[q] = 0ULL;
            accum_tile_T(w4s + f0 * WPAD, cur, p0, acc);
            __syncthreads();
#pragma unroll
            for (int ff = 0; ff < 4; ff++) {
                ulonglong2 st;
                st.x = fmul2(acc[2 * ff],     sd3[2 * ff]);
                st.y = fmul2(acc[2 * ff + 1], sd3[2 * ff + 1]);
                *reinterpret_cast<ulonglong2*>(&cur[f0 + ff][p0]) = st;
            }
        }
        __syncthreads();

        // ---- backward through W3 -> dz2 ----
        {
            u64 acc[8];
#pragma unroll
            for (int q = 0; q < 8; q++) acc[q] = 0ULL;
            accum_tile_T(w3s + f0 * WPAD, cur, p0, acc);
            __syncthreads();
#pragma unroll
            for (int ff = 0; ff < 4; ff++) {
                ulonglong2 st;
                st.x = fmul2(acc[2 * ff],     sd2[2 * ff]);
                st.y = fmul2(acc[2 * ff + 1], sd2[2 * ff + 1]);
                *reinterpret_cast<ulonglong2*>(&cur[f0 + ff][p0]) = st;
            }
        }
        __syncthreads();

        // ---- backward through W2 -> dz1 ----
        {
            u64 acc[8];
#pragma unroll
            for (int q = 0; q < 8; q++) acc[q] = 0ULL;
            accum_tile_T(w2s + f0 * WPAD, cur, p0, acc);
            __syncthreads();
#pragma unroll
            for (int ff = 0; ff < 4; ff++) {
                ulonglong2 st;
                st.x = fmul2(acc[2 * ff],     sd1[2 * ff]);
                st.y = fmul2(acc[2 * ff + 1], sd1[2 * ff + 1]);
                *reinterpret_cast<ulonglong2*>(&cur[f0 + ff][p0]) = st;
            }
        }
        __syncthreads();

        // ---- g = dz1 @ W1^T, clip, Langevin update ----
        {
            u64 gacc = 0ULL;
            const float* wrow = w1s + dd * 128 + part * 16;
#pragma unroll
            for (int jj = 0; jj < 16; jj++) {
                float w = wrow[jj];
                gacc = ffma2(cur[part * 16 + jj][spv], pack2(w, w), gacc);
            }
            gacc = fadd2(gacc, __shfl_down_sync(0xffffffffu, gacc, 4, 8));
            gacc = fadd2(gacc, __shfl_down_sync(0xffffffffu, gacc, 2, 8));
            gacc = fadd2(gacc, __shfl_down_sync(0xffffffffu, gacc, 1, 8));
            if (part == 0) {
                float2 g = unpack2(gacc);
                g.x = fminf(fmaxf(g.x, -0.03f), 0.03f);
                g.y = fminf(fmaxf(g.y, -0.03f), 0.03f);
                float2 xv = unpack2(xs[dd * 16 + spv]);
                float ax = xv.x + cn * nz0;  ax += eps * g.x;
                float ay = xv.y + cn * nz1;  ay += eps * g.y;
                ax = fminf(fmaxf(ax, -2.43f), 3.05f);
                ay = fminf(fmaxf(ay, -2.43f), 3.05f);
                xs[dd * 16 + spv] = pack2(ax, ay);
            }
        }
        __syncthreads();
    }

    // ---- write final x ----
    if (tid < 64) {
        int sl = tid >> 1, d = tid & 1;
        float2 v = unpack2(xs[d * 16 + (sl >> 1)]);
        out[(size_t)(s0 + sl) * 2 + d] = (sl & 1) ? v.y : v.x;
    }
}

extern "C" void kernel_launch(void* const* d_in, const int* in_sizes, int n_in,
                              void* d_out, int out_size) {
    const float* x0    = (const float*)d_in[0];
    const float* w1    = (const float*)d_in[1];
    const float* b1    = (const float*)d_in[2];
    const float* w2    = (const float*)d_in[3];
    const float* b2    = (const float*)d_in[4];
    const float* w3    = (const float*)d_in[5];
    const float* b3    = (const float*)d_in[6];
    const float* w4    = (const float*)d_in[7];
    const float* b4    = (const float*)d_in[8];
    const float* w5    = (const float*)d_in[9];
    const float* noise = (const float*)d_in[11];
    float* out = (float*)d_out;

    int nsamp = in_sizes[0] / 2;
    cudaFuncSetAttribute(ebm_mcmc_kernel,
                         cudaFuncAttributeMaxDynamicSharedMemorySize, SMEM_BYTES);
    int nblocks = nsamp / SB;
    ebm_mcmc_kernel<<<nblocks, 256, SMEM_BYTES>>>(
        x0, w1, b1, w2, b2, w3, b3, w4, b4, w5, noise, out, nsamp);
}

// round 7
// speedup vs baseline: 1.3614x; 1.0421x over previous
#include <cuda_runtime.h>

#define HDIM   128
#define NSTEPS 60
#define SB     64      // samples per block
#define NTHR   512
#define CPAD   32      // cur row length in u64 pairs

typedef unsigned long long u64;

// ---- f32x2 packed helpers ----
__device__ __forceinline__ u64 pack2(float a, float b) {
    u64 r; asm("mov.b64 %0, {%1, %2};" : "=l"(r) : "f"(a), "f"(b)); return r;
}
__device__ __forceinline__ float2 unpack2(u64 v) {
    float2 r; asm("mov.b64 {%0, %1}, %2;" : "=f"(r.x), "=f"(r.y) : "l"(v)); return r;
}
__device__ __forceinline__ u64 ffma2(u64 a, u64 b, u64 c) {
    u64 d; asm("fma.rn.f32x2 %0, %1, %2, %3;" : "=l"(d) : "l"(a), "l"(b), "l"(c)); return d;
}
__device__ __forceinline__ u64 fmul2(u64 a, u64 b) {
    u64 d; asm("mul.rn.f32x2 %0, %1, %2;" : "=l"(d) : "l"(a), "l"(b)); return d;
}
__device__ __forceinline__ u64 fadd2(u64 a, u64 b) {
    u64 d; asm("add.rn.f32x2 %0, %1, %2;" : "=l"(d) : "l"(a), "l"(b)); return d;
}

// silu + derivative, 2 lanes at a time
__device__ __forceinline__ void silu2(u64 z, u64& h, u64& d) {
    float2 zf = unpack2(z);
    float e0 = __expf(-zf.x), e1 = __expf(-zf.y);
    float s0 = 1.0f / (1.0f + e0), s1 = 1.0f / (1.0f + e1);
    float h0 = zf.x * s0,          h1 = zf.y * s1;
    float d0 = fmaf(h0, 1.0f - s0, s0);
    float d1 = fmaf(h1, 1.0f - s1, s1);
    h = pack2(h0, h1);
    d = pack2(d0, d1);
}

// Weight swizzle: element (r,c) stored at float index
//   r*128 + (((c>>2) ^ (r&31)) << 2) + (c&3)
// Forward reads row k, chunk f0>>2; backward reads row r, chunk k>>2.

// FORWARD: acc[2*ff+pp] += sum_k W[k][f0+ff] * cur[k][p0+pp]
__device__ __forceinline__ void accum_fwd(const float* __restrict__ ws, int cc,
                                          const u64 (*__restrict__ cur)[CPAD],
                                          int p0, u64 acc[8]) {
#pragma unroll 4
    for (int k = 0; k < HDIM; k++) {
        const float4 w = *reinterpret_cast<const float4*>(
            ws + k * 128 + (((k & 31) ^ cc) << 2));
        ulonglong2 h = *reinterpret_cast<const ulonglong2*>(&cur[k][p0]);
        u64 wa = pack2(w.x, w.x), wb = pack2(w.y, w.y);
        u64 wc = pack2(w.z, w.z), wd = pack2(w.w, w.w);
        acc[0] = ffma2(h.x, wa, acc[0]);  acc[1] = ffma2(h.y, wa, acc[1]);
        acc[2] = ffma2(h.x, wb, acc[2]);  acc[3] = ffma2(h.y, wb, acc[3]);
        acc[4] = ffma2(h.x, wc, acc[4]);  acc[5] = ffma2(h.y, wc, acc[5]);
        acc[6] = ffma2(h.x, wd, acc[6]);  acc[7] = ffma2(h.y, wd, acc[7]);
    }
}

// BACKWARD: acc[2*ff+pp] += sum_k W[f0+ff][k] * cur[k][p0+pp]
__device__ __forceinline__ void accum_bwd(const float* __restrict__ ws, int f0,
                                          const u64 (*__restrict__ cur)[CPAD],
                                          int p0, u64 acc[8]) {
    const float* r0b = ws + (f0 + 0) * 128;  const int x0m = (f0 + 0) & 31;
    const float* r1b = ws + (f0 + 1) * 128;  const int x1m = (f0 + 1) & 31;
    const float* r2b = ws + (f0 + 2) * 128;  const int x2m = (f0 + 2) & 31;
    const float* r3b = ws + (f0 + 3) * 128;  const int x3m = (f0 + 3) & 31;
#pragma unroll 4
    for (int k = 0; k < HDIM; k += 4) {
        int cc = k >> 2;
        float4 w0 = *reinterpret_cast<const float4*>(r0b + ((cc ^ x0m) << 2));
        float4 w1 = *reinterpret_cast<const float4*>(r1b + ((cc ^ x1m) << 2));
        float4 w2 = *reinterpret_cast<const float4*>(r2b + ((cc ^ x2m) << 2));
        float4 w3 = *reinterpret_cast<const float4*>(r3b + ((cc ^ x3m) << 2));
        ulonglong2 h0 = *reinterpret_cast<const ulonglong2*>(&cur[k + 0][p0]);
        ulonglong2 h1 = *reinterpret_cast<const ulonglong2*>(&cur[k + 1][p0]);
        ulonglong2 h2 = *reinterpret_cast<const ulonglong2*>(&cur[k + 2][p0]);
        ulonglong2 h3 = *reinterpret_cast<const ulonglong2*>(&cur[k + 3][p0]);

        acc[0] = ffma2(h0.x, pack2(w0.x, w0.x), acc[0]);
        acc[1] = ffma2(h0.y, pack2(w0.x, w0.x), acc[1]);
        acc[0] = ffma2(h1.x, pack2(w0.y, w0.y), acc[0]);
        acc[1] = ffma2(h1.y, pack2(w0.y, w0.y), acc[1]);
        acc[0] = ffma2(h2.x, pack2(w0.z, w0.z), acc[0]);
        acc[1] = ffma2(h2.y, pack2(w0.z, w0.z), acc[1]);
        acc[0] = ffma2(h3.x, pack2(w0.w, w0.w), acc[0]);
        acc[1] = ffma2(h3.y, pack2(w0.w, w0.w), acc[1]);

        acc[2] = ffma2(h0.x, pack2(w1.x, w1.x), acc[2]);
        acc[3] = ffma2(h0.y, pack2(w1.x, w1.x), acc[3]);
        acc[2] = ffma2(h1.x, pack2(w1.y, w1.y), acc[2]);
        acc[3] = ffma2(h1.y, pack2(w1.y, w1.y), acc[3]);
        acc[2] = ffma2(h2.x, pack2(w1.z, w1.z), acc[2]);
        acc[3] = ffma2(h2.y, pack2(w1.z, w1.z), acc[3]);
        acc[2] = ffma2(h3.x, pack2(w1.w, w1.w), acc[2]);
        acc[3] = ffma2(h3.y, pack2(w1.w, w1.w), acc[3]);

        acc[4] = ffma2(h0.x, pack2(w2.x, w2.x), acc[4]);
        acc[5] = ffma2(h0.y, pack2(w2.x, w2.x), acc[5]);
        acc[4] = ffma2(h1.x, pack2(w2.y, w2.y), acc[4]);
        acc[5] = ffma2(h1.y, pack2(w2.y, w2.y), acc[5]);
        acc[4] = ffma2(h2.x, pack2(w2.z, w2.z), acc[4]);
        acc[5] = ffma2(h2.y, pack2(w2.z, w2.z), acc[5]);
        acc[4] = ffma2(h3.x, pack2(w2.w, w2.w), acc[4]);
        acc[5] = ffma2(h3.y, pack2(w2.w, w2.w), acc[5]);

        acc[6] = ffma2(h0.x, pack2(w3.x, w3.x), acc[6]);
        acc[7] = ffma2(h0.y, pack2(w3.x, w3.x), acc[7]);
        acc[6] = ffma2(h1.x, pack2(w3.y, w3.y), acc[6]);
        acc[7] = ffma2(h1.y, pack2(w3.y, w3.y), acc[7]);
        acc[6] = ffma2(h2.x, pack2(w3.z, w3.z), acc[6]);
        acc[7] = ffma2(h2.y, pack2(w3.z, w3.z), acc[7]);
        acc[6] = ffma2(h3.x, pack2(w3.w, w3.w), acc[6]);
        acc[7] = ffma2(h3.y, pack2(w3.w, w3.w), acc[7]);
    }
}

// SMEM layout (bytes):
//   cur  : 0       u64[128][32]      = 32768
//   w2s  : 32768   float[128*128]    = 65536
//   w3s  : 98304
//   w4s  : 163840
//   w1s  : 229376  float[256]        = 1024
//   b2s  : 230400  float[128]
//   b3s  : 230912
//   b4s  : 231424
//   xs   : 231936  u64[64]           = 512   -> total 232448 (= 227KB cap)
#define SMEM_BYTES 232448

__global__ void __launch_bounds__(NTHR, 1)
ebm_mcmc_kernel(const float* __restrict__ x0,
                const float* __restrict__ w1, const float* __restrict__ b1,
                const float* __restrict__ w2, const float* __restrict__ b2,
                const float* __restrict__ w3, const float* __restrict__ b3,
                const float* __restrict__ w4, const float* __restrict__ b4,
                const float* __restrict__ w5,
                const float* __restrict__ noise,
                float* __restrict__ out, int nsamp) {
    extern __shared__ unsigned char smraw[];
    u64 (*cur)[CPAD] = reinterpret_cast<u64(*)[CPAD]>(smraw);
    float* w2s = reinterpret_cast<float*>(smraw + 32768);
    float* w3s = w2s + HDIM * 128;
    float* w4s = w3s + HDIM * 128;
    float* w1s = w4s + HDIM * 128;    // [2][128]
    float* b2s = w1s + 256;
    float* b3s = b2s + 128;
    float* b4s = b3s + 128;
    u64*   xs  = reinterpret_cast<u64*>(b4s + 128);   // xs[d*32 + p]

    const int tid = threadIdx.x;
    const int f0  = (tid >> 4) * 4;   // 4 contiguous output features
    const int cc0 = f0 >> 2;
    const int p0  = (tid & 15) * 2;   // 2 contiguous sample-pairs
    const int s0  = blockIdx.x * SB;

    // ---- load weights into SMEM (swizzled), once per block ----
    for (int idx = tid; idx < HDIM * HDIM; idx += NTHR) {
        int r = idx >> 7, c = idx & 127;
        int o = r * 128 + ((((c >> 2) ^ (r & 31)) << 2) | (c & 3));
        w2s[o] = w2[idx];
        w3s[o] = w3[idx];
        w4s[o] = w4[idx];
    }
    if (tid < 256) w1s[tid] = w1[tid];
    if (tid < 128) {
        b2s[tid] = b2[tid];
        b3s[tid] = b3[tid];
        b4s[tid] = b4[tid];
    }
    if (tid < 64) {
        int d = tid >> 5, p = tid & 31;
        size_t bx = (size_t)(s0 + 2 * p) * 2 + d;
        xs[tid] = pack2(x0[bx], x0[bx + 2]);
    }
    // per-thread constants from global (cached in regs for all 60 steps)
    const float4 b1r = *reinterpret_cast<const float4*>(b1 + f0);
    const float4 w5r = *reinterpret_cast<const float4*>(w5 + f0);
    __syncthreads();

    // silu' in registers for layers 2,3 (sd1 recomputed; sd4 transient)
    u64 sd2[8], sd3[8];

    const int part = tid & 7;        // final-matmul j partition
    const int oid  = tid >> 3;       // 0..63
    const int pd   = oid >> 5;       // dim
    const int pp   = oid & 31;       // pair

    for (int i = 0; i < NSTEPS; i++) {
        float fi  = (float)i;
        float eps = 10.0f * (1.0f - fi / 60.0f);
        float cn  = sqrtf(2.0f * eps) * 0.005f;

        // prefetch this step's noise (consumed at step end)
        float nz0 = 0.0f, nz1 = 0.0f;
        if (part == 0) {
            size_t base = ((size_t)i * nsamp + s0 + 2 * pp) * 2 + pd;
            nz0 = noise[base];
            nz1 = noise[base + 2];
        }

        // ---- forward L1 ----
        {
            float4 wa = *reinterpret_cast<const float4*>(w1s + f0);
            float4 wb = *reinterpret_cast<const float4*>(w1s + 128 + f0);
            u64 xa0 = xs[p0], xa1 = xs[p0 + 1];
            u64 xb0 = xs[32 + p0], xb1 = xs[32 + p0 + 1];
            float wav[4] = {wa.x, wa.y, wa.z, wa.w};
            float wbv[4] = {wb.x, wb.y, wb.z, wb.w};
            float bbv[4] = {b1r.x, b1r.y, b1r.z, b1r.w};
#pragma unroll
            for (int ff = 0; ff < 4; ff++) {
                u64 wap = pack2(wav[ff], wav[ff]);
                u64 wbp = pack2(wbv[ff], wbv[ff]);
                u64 bbp = pack2(bbv[ff], bbv[ff]);
                u64 z0 = ffma2(xa0, wap, ffma2(xb0, wbp, bbp));
                u64 z1 = ffma2(xa1, wap, ffma2(xb1, wbp, bbp));
                u64 h0, d0, h1, d1;
                silu2(z0, h0, d0);  silu2(z1, h1, d1);
                (void)d0; (void)d1;   // sd1 recomputed later
                ulonglong2 st; st.x = h0; st.y = h1;
                *reinterpret_cast<ulonglong2*>(&cur[f0 + ff][p0]) = st;
            }
        }
        __syncthreads();

        // ---- forward L2 ----
        {
            u64 acc[8];
            float4 bb = *reinterpret_cast<const float4*>(b2s + f0);
            acc[0] = acc[1] = pack2(bb.x, bb.x);
            acc[2] = acc[3] = pack2(bb.y, bb.y);
            acc[4] = acc[5] = pack2(bb.z, bb.z);
            acc[6] = acc[7] = pack2(bb.w, bb.w);
            accum_fwd(w2s, cc0, cur, p0, acc);
            __syncthreads();
#pragma unroll
            for (int ff = 0; ff < 4; ff++) {
                u64 h0, d0, h1, d1;
                silu2(acc[2 * ff], h0, d0);  silu2(acc[2 * ff + 1], h1, d1);
                sd2[2 * ff] = d0;  sd2[2 * ff + 1] = d1;
                ulonglong2 st; st.x = h0; st.y = h1;
                *reinterpret_cast<ulonglong2*>(&cur[f0 + ff][p0]) = st;
            }
        }
        __syncthreads();

        // ---- forward L3 ----
        {
            u64 acc[8];
            float4 bb = *reinterpret_cast<const float4*>(b3s + f0);
            acc[0] = acc[1] = pack2(bb.x, bb.x);
            acc[2] = acc[3] = pack2(bb.y, bb.y);
            acc[4] = acc[5] = pack2(bb.z, bb.z);
            acc[6] = acc[7] = pack2(bb.w, bb.w);
            accum_fwd(w3s, cc0, cur, p0, acc);
            __syncthreads();
#pragma unroll
            for (int ff = 0; ff < 4; ff++) {
                u64 h0, d0, h1, d1;
                silu2(acc[2 * ff], h0, d0);  silu2(acc[2 * ff + 1], h1, d1);
                sd3[2 * ff] = d0;  sd3[2 * ff + 1] = d1;
                ulonglong2 st; st.x = h0; st.y = h1;
                *reinterpret_cast<ulonglong2*>(&cur[f0 + ff][p0]) = st;
            }
        }
        __syncthreads();

        // ---- forward L4 (h4 dead) + backward seed dz4 = w5 .* silu'(z4) ----
        {
            u64 acc[8];
            float4 bb = *reinterpret_cast<const float4*>(b4s + f0);
            acc[0] = acc[1] = pack2(bb.x, bb.x);
            acc[2] = acc[3] = pack2(bb.y, bb.y);
            acc[4] = acc[5] = pack2(bb.z, bb.z);
            acc[6] = acc[7] = pack2(bb.w, bb.w);
            accum_fwd(w4s, cc0, cur, p0, acc);
            float w5a[4] = {w5r.x, w5r.y, w5r.z, w5r.w};
            u64 dz[8];
#pragma unroll
            for (int ff = 0; ff < 4; ff++) {
                u64 h0, d0, h1, d1;
                silu2(acc[2 * ff], h0, d0);  silu2(acc[2 * ff + 1], h1, d1);
                u64 wp = pack2(w5a[ff], w5a[ff]);
                dz[2 * ff]     = fmul2(wp, d0);
                dz[2 * ff + 1] = fmul2(wp, d1);
            }
            __syncthreads();   // all reads of h3 from cur done
#pragma unroll
            for (int ff = 0; ff < 4; ff++) {
                ulonglong2 st; st.x = dz[2 * ff]; st.y = dz[2 * ff + 1];
                *reinterpret_cast<ulonglong2*>(&cur[f0 + ff][p0]) = st;
            }
        }
        __syncthreads();

        // ---- backward W4: dz3 = (dz4 @ W4^T) .* silu'(z3) ----
        {
            u64 acc[8];
#pragma unroll
            for (int q = 0; q < 8; q++) acc[q] = 0ULL;
            accum_bwd(w4s, f0, cur, p0, acc);
            __syncthreads();
#pragma unroll
            for (int ff = 0; ff < 4; ff++) {
                ulonglong2 st;
                st.x = fmul2(acc[2 * ff],     sd3[2 * ff]);
                st.y = fmul2(acc[2 * ff + 1], sd3[2 * ff + 1]);
                *reinterpret_cast<ulonglong2*>(&cur[f0 + ff][p0]) = st;
            }
        }
        __syncthreads();

        // ---- backward W3 -> dz2 ----
        {
            u64 acc[8];
#pragma unroll
            for (int q = 0; q < 8; q++) acc[q] = 0ULL;
            accum_bwd(w3s, f0, cur, p0, acc);
            __syncthreads();
#pragma unroll
            for (int ff = 0; ff < 4; ff++) {
                ulonglong2 st;
                st.x = fmul2(acc[2 * ff],     sd2[2 * ff]);
                st.y = fmul2(acc[2 * ff + 1], sd2[2 * ff + 1]);
                *reinterpret_cast<ulonglong2*>(&cur[f0 + ff][p0]) = st;
            }
        }
        __syncthreads();

        // ---- backward W2 -> dz1 (sd1 recomputed here) ----
        {
            u64 acc[8];
#pragma unroll
            for (int q = 0; q < 8; q++) acc[q] = 0ULL;
            accum_bwd(w2s, f0, cur, p0, acc);
            // recompute sd1 = silu'(x @ W1 + b1)
            float4 wa = *reinterpret_cast<const float4*>(w1s + f0);
            float4 wb = *reinterpret_cast<const float4*>(w1s + 128 + f0);
            u64 xa0 = xs[p0], xa1 = xs[p0 + 1];
            u64 xb0 = xs[32 + p0], xb1 = xs[32 + p0 + 1];
            float wav[4] = {wa.x, wa.y, wa.z, wa.w};
            float wbv[4] = {wb.x, wb.y, wb.z, wb.w};
            float bbv[4] = {b1r.x, b1r.y, b1r.z, b1r.w};
            u64 dzv[8];
#pragma unroll
            for (int ff = 0; ff < 4; ff++) {
                u64 wap = pack2(wav[ff], wav[ff]);
                u64 wbp = pack2(wbv[ff], wbv[ff]);
                u64 bbp = pack2(bbv[ff], bbv[ff]);
                u64 z0 = ffma2(xa0, wap, ffma2(xb0, wbp, bbp));
                u64 z1 = ffma2(xa1, wap, ffma2(xb1, wbp, bbp));
                u64 h0, d0, h1, d1;
                silu2(z0, h0, d0);  silu2(z1, h1, d1);
                dzv[2 * ff]     = fmul2(acc[2 * ff],     d0);
                dzv[2 * ff + 1] = fmul2(acc[2 * ff + 1], d1);
            }
            __syncthreads();
#pragma unroll
            for (int ff = 0; ff < 4; ff++) {
                ulonglong2 st; st.x = dzv[2 * ff]; st.y = dzv[2 * ff + 1];
                *reinterpret_cast<ulonglong2*>(&cur[f0 + ff][p0]) = st;
            }
        }
        __syncthreads();

        // ---- g = dz1 @ W1^T, clip, Langevin update ----
        {
            u64 gacc = 0ULL;
            const float* wrow = w1s + pd * 128 + part * 16;
            const u64 (*crow)[CPAD] = cur + part * 16;
#pragma unroll
            for (int jj = 0; jj < 16; jj++) {
                float w = wrow[jj];
                gacc = ffma2(crow[jj][pp], pack2(w, w), gacc);
            }
            gacc = fadd2(gacc, __shfl_down_sync(0xffffffffu, gacc, 4, 8));
            gacc = fadd2(gacc, __shfl_down_sync(0xffffffffu, gacc, 2, 8));
            gacc = fadd2(gacc, __shfl_down_sync(0xffffffffu, gacc, 1, 8));
            if (part == 0) {
                float2 g = unpack2(gacc);
                g.x = fminf(fmaxf(g.x, -0.03f), 0.03f);
                g.y = fminf(fmaxf(g.y, -0.03f), 0.03f);
                float2 xv = unpack2(xs[pd * 32 + pp]);
                float ax = xv.x + cn * nz0;  ax += eps * g.x;
                float ay = xv.y + cn * nz1;  ay += eps * g.y;
                ax = fminf(fmaxf(ax, -2.43f), 3.05f);
                ay = fminf(fmaxf(ay, -2.43f), 3.05f);
                xs[pd * 32 + pp] = pack2(ax, ay);
            }
        }
        __syncthreads();
    }

    // ---- write final x ----
    if (tid < 128) {
        int s = tid >> 1, d = tid & 1;
        float2 v = unpack2(xs[d * 32 + (s >> 1)]);
        out[(size_t)(s0 + s) * 2 + d] = (s & 1) ? v.y : v.x;
    }
}

extern "C" void kernel_launch(void* const* d_in, const int* in_sizes, int n_in,
                              void* d_out, int out_size) {
    const float* x0    = (const float*)d_in[0];
    const float* w1    = (const float*)d_in[1];
    const float* b1    = (const float*)d_in[2];
    const float* w2    = (const float*)d_in[3];
    const float* b2    = (const float*)d_in[4];
    const float* w3    = (const float*)d_in[5];
    const float* b3    = (const float*)d_in[6];
    const float* w4    = (const float*)d_in[7];
    const float* b4    = (const float*)d_in[8];
    const float* w5    = (const float*)d_in[9];
    const float* noise = (const float*)d_in[11];
    float* out = (float*)d_out;

    int nsamp = in_sizes[0] / 2;
    cudaFuncSetAttribute(ebm_mcmc_kernel,
                         cudaFuncAttributeMaxDynamicSharedMemorySize, SMEM_BYTES);
    int nblocks = nsamp / SB;
    ebm_mcmc_kernel<<<nblocks, NTHR, SMEM_BYTES>>>(
        x0, w1, b1, w2, b2, w3, b3, w4, b4, w5, noise, out, nsamp);
}

// round 10
// speedup vs baseline: 1.3626x; 1.0009x over previous
#include <cuda_runtime.h>

#define HDIM   128
#define NSTEPS 60
#define SB     64      // samples per block
#define NTHR   512
#define CPAD   32      // cur row length in u64 pairs

typedef unsigned long long u64;

// ---- f32x2 packed helpers ----
__device__ __forceinline__ u64 pack2(float a, float b) {
    u64 r; asm("mov.b64 %0, {%1, %2};" : "=l"(r) : "f"(a), "f"(b)); return r;
}
__device__ __forceinline__ float2 unpack2(u64 v) {
    float2 r; asm("mov.b64 {%0, %1}, %2;" : "=f"(r.x), "=f"(r.y) : "l"(v)); return r;
}
__device__ __forceinline__ u64 ffma2(u64 a, u64 b, u64 c) {
    u64 d; asm("fma.rn.f32x2 %0, %1, %2, %3;" : "=l"(d) : "l"(a), "l"(b), "l"(c)); return d;
}
__device__ __forceinline__ u64 fmul2(u64 a, u64 b) {
    u64 d; asm("mul.rn.f32x2 %0, %1, %2;" : "=l"(d) : "l"(a), "l"(b)); return d;
}
__device__ __forceinline__ u64 fadd2(u64 a, u64 b) {
    u64 d; asm("add.rn.f32x2 %0, %1, %2;" : "=l"(d) : "l"(a), "l"(b)); return d;
}

// silu + derivative, 2 lanes at a time
__device__ __forceinline__ void silu2(u64 z, u64& h, u64& d) {
    float2 zf = unpack2(z);
    float e0 = __expf(-zf.x), e1 = __expf(-zf.y);
    float s0 = 1.0f / (1.0f + e0), s1 = 1.0f / (1.0f + e1);
    float h0 = zf.x * s0,          h1 = zf.y * s1;
    float d0 = fmaf(h0, 1.0f - s0, s0);
    float d1 = fmaf(h1, 1.0f - s1, s1);
    h = pack2(h0, h1);
    d = pack2(d0, d1);
}

// Weight swizzle: element (r,c) stored at float index
//   r*128 + (((c>>2) ^ (r&31)) << 2) + (c&3)
// Forward reads row k, chunk f0>>2; backward reads row r, chunk k>>2.

// FORWARD: acc[2*ff+pp] += sum_k W[k][f0+ff] * cur[k][p0+pp]
__device__ __forceinline__ void accum_fwd(const float* __restrict__ ws, int cc,
                                          const u64 (*__restrict__ cur)[CPAD],
                                          int p0, u64 acc[8]) {
#pragma unroll 4
    for (int k = 0; k < HDIM; k++) {
        const float4 w = *reinterpret_cast<const float4*>(
            ws + k * 128 + (((k & 31) ^ cc) << 2));
        ulonglong2 h = *reinterpret_cast<const ulonglong2*>(&cur[k][p0]);
        u64 wa = pack2(w.x, w.x), wb = pack2(w.y, w.y);
        u64 wc = pack2(w.z, w.z), wd = pack2(w.w, w.w);
        acc[0] = ffma2(h.x, wa, acc[0]);  acc[1] = ffma2(h.y, wa, acc[1]);
        acc[2] = ffma2(h.x, wb, acc[2]);  acc[3] = ffma2(h.y, wb, acc[3]);
        acc[4] = ffma2(h.x, wc, acc[4]);  acc[5] = ffma2(h.y, wc, acc[5]);
        acc[6] = ffma2(h.x, wd, acc[6]);  acc[7] = ffma2(h.y, wd, acc[7]);
    }
}

// BACKWARD: acc[2*ff+pp] += sum_k W[f0+ff][k] * cur[k][p0+pp]
__device__ __forceinline__ void accum_bwd(const float* __restrict__ ws, int f0,
                                          const u64 (*__restrict__ cur)[CPAD],
                                          int p0, u64 acc[8]) {
    const float* r0b = ws + (f0 + 0) * 128;  const int x0m = (f0 + 0) & 31;
    const float* r1b = ws + (f0 + 1) * 128;  const int x1m = (f0 + 1) & 31;
    const float* r2b = ws + (f0 + 2) * 128;  const int x2m = (f0 + 2) & 31;
    const float* r3b = ws + (f0 + 3) * 128;  const int x3m = (f0 + 3) & 31;
#pragma unroll 4
    for (int k = 0; k < HDIM; k += 4) {
        int cc = k >> 2;
        float4 w0 = *reinterpret_cast<const float4*>(r0b + ((cc ^ x0m) << 2));
        float4 w1 = *reinterpret_cast<const float4*>(r1b + ((cc ^ x1m) << 2));
        float4 w2 = *reinterpret_cast<const float4*>(r2b + ((cc ^ x2m) << 2));
        float4 w3 = *reinterpret_cast<const float4*>(r3b + ((cc ^ x3m) << 2));
        ulonglong2 h0 = *reinterpret_cast<const ulonglong2*>(&cur[k + 0][p0]);
        ulonglong2 h1 = *reinterpret_cast<const ulonglong2*>(&cur[k + 1][p0]);
        ulonglong2 h2 = *reinterpret_cast<const ulonglong2*>(&cur[k + 2][p0]);
        ulonglong2 h3 = *reinterpret_cast<const ulonglong2*>(&cur[k + 3][p0]);

        acc[0] = ffma2(h0.x, pack2(w0.x, w0.x), acc[0]);
        acc[1] = ffma2(h0.y, pack2(w0.x, w0.x), acc[1]);
        acc[0] = ffma2(h1.x, pack2(w0.y, w0.y), acc[0]);
        acc[1] = ffma2(h1.y, pack2(w0.y, w0.y), acc[1]);
        acc[0] = ffma2(h2.x, pack2(w0.z, w0.z), acc[0]);
        acc[1] = ffma2(h2.y, pack2(w0.z, w0.z), acc[1]);
        acc[0] = ffma2(h3.x, pack2(w0.w, w0.w), acc[0]);
        acc[1] = ffma2(h3.y, pack2(w0.w, w0.w), acc[1]);

        acc[2] = ffma2(h0.x, pack2(w1.x, w1.x), acc[2]);
        acc[3] = ffma2(h0.y, pack2(w1.x, w1.x), acc[3]);
        acc[2] = ffma2(h1.x, pack2(w1.y, w1.y), acc[2]);
        acc[3] = ffma2(h1.y, pack2(w1.y, w1.y), acc[3]);
        acc[2] = ffma2(h2.x, pack2(w1.z, w1.z), acc[2]);
        acc[3] = ffma2(h2.y, pack2(w1.z, w1.z), acc[3]);
        acc[2] = ffma2(h3.x, pack2(w1.w, w1.w), acc[2]);
        acc[3] = ffma2(h3.y, pack2(w1.w, w1.w), acc[3]);

        acc[4] = ffma2(h0.x, pack2(w2.x, w2.x), acc[4]);
        acc[5] = ffma2(h0.y, pack2(w2.x, w2.x), acc[5]);
        acc[4] = ffma2(h1.x, pack2(w2.y, w2.y), acc[4]);
        acc[5] = ffma2(h1.y, pack2(w2.y, w2.y), acc[5]);
        acc[4] = ffma2(h2.x, pack2(w2.z, w2.z), acc[4]);
        acc[5] = ffma2(h2.y, pack2(w2.z, w2.z), acc[5]);
        acc[4] = ffma2(h3.x, pack2(w2.w, w2.w), acc[4]);
        acc[5] = ffma2(h3.y, pack2(w2.w, w2.w), acc[5]);

        acc[6] = ffma2(h0.x, pack2(w3.x, w3.x), acc[6]);
        acc[7] = ffma2(h0.y, pack2(w3.x, w3.x), acc[7]);
        acc[6] = ffma2(h1.x, pack2(w3.y, w3.y), acc[6]);
        acc[7] = ffma2(h1.y, pack2(w3.y, w3.y), acc[7]);
        acc[6] = ffma2(h2.x, pack2(w3.z, w3.z), acc[6]);
        acc[7] = ffma2(h2.y, pack2(w3.z, w3.z), acc[7]);
        acc[6] = ffma2(h3.x, pack2(w3.w, w3.w), acc[6]);
        acc[7] = ffma2(h3.y, pack2(w3.w, w3.w), acc[7]);
    }
}

// SMEM layout (bytes):
//   cur  : 0       u64[128][32]      = 32768
//   w2s  : 32768   float[128*128]    = 65536
//   w3s  : 98304
//   w4s  : 163840
//   w1s  : 229376  float[256]        = 1024
//   b2s  : 230400  float[128]
//   b3s  : 230912
//   b4s  : 231424
//   xs   : 231936  u64[64]           = 512   -> total 232448 (= 227KB cap)
#define SMEM_BYTES 232448

__global__ void __launch_bounds__(NTHR, 1)
ebm_mcmc_kernel(const float* __restrict__ x0,
                const float* __restrict__ w1, const float* __restrict__ b1,
                const float* __restrict__ w2, const float* __restrict__ b2,
                const float* __restrict__ w3, const float* __restrict__ b3,
                const float* __restrict__ w4, const float* __restrict__ b4,
                const float* __restrict__ w5,
                const float* __restrict__ noise,
                float* __restrict__ out, int nsamp) {
    extern __shared__ unsigned char smraw[];
    u64 (*cur)[CPAD] = reinterpret_cast<u64(*)[CPAD]>(smraw);
    float* w2s = reinterpret_cast<float*>(smraw + 32768);
    float* w3s = w2s + HDIM * 128;
    float* w4s = w3s + HDIM * 128;
    float* w1s = w4s + HDIM * 128;    // [2][128]
    float* b2s = w1s + 256;
    float* b3s = b2s + 128;
    float* b4s = b3s + 128;
    u64*   xs  = reinterpret_cast<u64*>(b4s + 128);   // xs[d*32 + p]

    const int tid = threadIdx.x;
    const int f0  = (tid >> 4) * 4;   // 4 contiguous output features
    const int cc0 = f0 >> 2;
    const int p0  = (tid & 15) * 2;   // 2 contiguous sample-pairs
    const int s0  = blockIdx.x * SB;

    // ---- load weights into SMEM (swizzled), once per block ----
    for (int idx = tid; idx < HDIM * HDIM; idx += NTHR) {
        int r = idx >> 7, c = idx & 127;
        int o = r * 128 + ((((c >> 2) ^ (r & 31)) << 2) | (c & 3));
        w2s[o] = w2[idx];
        w3s[o] = w3[idx];
        w4s[o] = w4[idx];
    }
    if (tid < 256) w1s[tid] = w1[tid];
    if (tid < 128) {
        b2s[tid] = b2[tid];
        b3s[tid] = b3[tid];
        b4s[tid] = b4[tid];
    }
    if (tid < 64) {
        int d = tid >> 5, p = tid & 31;
        size_t bx = (size_t)(s0 + 2 * p) * 2 + d;
        xs[tid] = pack2(x0[bx], x0[bx + 2]);
    }
    // per-thread constants from global (cached in regs for all 60 steps)
    const float4 b1r = *reinterpret_cast<const float4*>(b1 + f0);
    const float4 w5r = *reinterpret_cast<const float4*>(w5 + f0);
    __syncthreads();

    // silu' in registers for layers 2,3 (sd1 recomputed; sd4 transient)
    u64 sd2[8], sd3[8];

    const int part = tid & 7;        // final-matmul j partition
    const int oid  = tid >> 3;       // 0..63
    const int pd   = oid >> 5;       // dim
    const int pp   = oid & 31;       // pair

    for (int i = 0; i < NSTEPS; i++) {
        float fi  = (float)i;
        float eps = 10.0f * (1.0f - fi / 60.0f);
        float cn  = sqrtf(2.0f * eps) * 0.005f;

        // prefetch this step's noise (consumed at step end)
        float nz0 = 0.0f, nz1 = 0.0f;
        if (part == 0) {
            size_t base = ((size_t)i * nsamp + s0 + 2 * pp) * 2 + pd;
            nz0 = noise[base];
            nz1 = noise[base + 2];
        }

        // ---- forward L1 ----
        {
            float4 wa = *reinterpret_cast<const float4*>(w1s + f0);
            float4 wb = *reinterpret_cast<const float4*>(w1s + 128 + f0);
            u64 xa0 = xs[p0], xa1 = xs[p0 + 1];
            u64 xb0 = xs[32 + p0], xb1 = xs[32 + p0 + 1];
            float wav[4] = {wa.x, wa.y, wa.z, wa.w};
            float wbv[4] = {wb.x, wb.y, wb.z, wb.w};
            float bbv[4] = {b1r.x, b1r.y, b1r.z, b1r.w};
#pragma unroll
            for (int ff = 0; ff < 4; ff++) {
                u64 wap = pack2(wav[ff], wav[ff]);
                u64 wbp = pack2(wbv[ff], wbv[ff]);
                u64 bbp = pack2(bbv[ff], bbv[ff]);
                u64 z0 = ffma2(xa0, wap, ffma2(xb0, wbp, bbp));
                u64 z1 = ffma2(xa1, wap, ffma2(xb1, wbp, bbp));
                u64 h0, d0, h1, d1;
                silu2(z0, h0, d0);  silu2(z1, h1, d1);
                (void)d0; (void)d1;   // sd1 recomputed later
                ulonglong2 st; st.x = h0; st.y = h1;
                *reinterpret_cast<ulonglong2*>(&cur[f0 + ff][p0]) = st;
            }
        }
        __syncthreads();

        // ---- forward L2 ----
        {
            u64 acc[8];
            float4 bb = *reinterpret_cast<const float4*>(b2s + f0);
            acc[0] = acc[1] = pack2(bb.x, bb.x);
            acc[2] = acc[3] = pack2(bb.y, bb.y);
            acc[4] = acc[5] = pack2(bb.z, bb.z);
            acc[6] = acc[7] = pack2(bb.w, bb.w);
            accum_fwd(w2s, cc0, cur, p0, acc);
            __syncthreads();
#pragma unroll
            for (int ff = 0; ff < 4; ff++) {
                u64 h0, d0, h1, d1;
                silu2(acc[2 * ff], h0, d0);  silu2(acc[2 * ff + 1], h1, d1);
                sd2[2 * ff] = d0;  sd2[2 * ff + 1] = d1;
                ulonglong2 st; st.x = h0; st.y = h1;
                *reinterpret_cast<ulonglong2*>(&cur[f0 + ff][p0]) = st;
            }
        }
        __syncthreads();

        // ---- forward L3 ----
        {
            u64 acc[8];
            float4 bb = *reinterpret_cast<const float4*>(b3s + f0);
            acc[0] = acc[1] = pack2(bb.x, bb.x);
            acc[2] = acc[3] = pack2(bb.y, bb.y);
            acc[4] = acc[5] = pack2(bb.z, bb.z);
            acc[6] = acc[7] = pack2(bb.w, bb.w);
            accum_fwd(w3s, cc0, cur, p0, acc);
            __syncthreads();
#pragma unroll
            for (int ff = 0; ff < 4; ff++) {
                u64 h0, d0, h1, d1;
                silu2(acc[2 * ff], h0, d0);  silu2(acc[2 * ff + 1], h1, d1);
                sd3[2 * ff] = d0;  sd3[2 * ff + 1] = d1;
                ulonglong2 st; st.x = h0; st.y = h1;
                *reinterpret_cast<ulonglong2*>(&cur[f0 + ff][p0]) = st;
            }
        }
        __syncthreads();

        // ---- forward L4 (h4 dead) + backward seed dz4 = w5 .* silu'(z4) ----
        {
            u64 acc[8];
            float4 bb = *reinterpret_cast<const float4*>(b4s + f0);
            acc[0] = acc[1] = pack2(bb.x, bb.x);
            acc[2] = acc[3] = pack2(bb.y, bb.y);
            acc[4] = acc[5] = pack2(bb.z, bb.z);
            acc[6] = acc[7] = pack2(bb.w, bb.w);
            accum_fwd(w4s, cc0, cur, p0, acc);
            float w5a[4] = {w5r.x, w5r.y, w5r.z, w5r.w};
            u64 dz[8];
#pragma unroll
            for (int ff = 0; ff < 4; ff++) {
                u64 h0, d0, h1, d1;
                silu2(acc[2 * ff], h0, d0);  silu2(acc[2 * ff + 1], h1, d1);
                u64 wp = pack2(w5a[ff], w5a[ff]);
                dz[2 * ff]     = fmul2(wp, d0);
                dz[2 * ff + 1] = fmul2(wp, d1);
            }
            __syncthreads();   // all reads of h3 from cur done
#pragma unroll
            for (int ff = 0; ff < 4; ff++) {
                ulonglong2 st; st.x = dz[2 * ff]; st.y = dz[2 * ff + 1];
                *reinterpret_cast<ulonglong2*>(&cur[f0 + ff][p0]) = st;
            }
        }
        __syncthreads();

        // ---- backward W4: dz3 = (dz4 @ W4^T) .* silu'(z3) ----
        {
            u64 acc[8];
#pragma unroll
            for (int q = 0; q < 8; q++) acc[q] = 0ULL;
            accum_bwd(w4s, f0, cur, p0, acc);
            __syncthreads();
#pragma unroll
            for (int ff = 0; ff < 4; ff++) {
                ulonglong2 st;
                st.x = fmul2(acc[2 * ff],     sd3[2 * ff]);
                st.y = fmul2(acc[2 * ff + 1], sd3[2 * ff + 1]);
                *reinterpret_cast<ulonglong2*>(&cur[f0 + ff][p0]) = st;
            }
        }
        __syncthreads();

        // ---- backward W3 -> dz2 ----
        {
            u64 acc[8];
#pragma unroll
            for (int q = 0; q < 8; q++) acc[q] = 0ULL;
            accum_bwd(w3s, f0, cur, p0, acc);
            __syncthreads();
#pragma unroll
            for (int ff = 0; ff < 4; ff++) {
                ulonglong2 st;
                st.x = fmul2(acc[2 * ff],     sd2[2 * ff]);
                st.y = fmul2(acc[2 * ff + 1], sd2[2 * ff + 1]);
                *reinterpret_cast<ulonglong2*>(&cur[f0 + ff][p0]) = st;
            }
        }
        __syncthreads();

        // ---- backward W2 -> dz1 (sd1 recomputed here) ----
        {
            u64 acc[8];
#pragma unroll
            for (int q = 0; q < 8; q++) acc[q] = 0ULL;
            accum_bwd(w2s, f0, cur, p0, acc);
            // recompute sd1 = silu'(x @ W1 + b1)
            float4 wa = *reinterpret_cast<const float4*>(w1s + f0);
            float4 wb = *reinterpret_cast<const float4*>(w1s + 128 + f0);
            u64 xa0 = xs[p0], xa1 = xs[p0 + 1];
            u64 xb0 = xs[32 + p0], xb1 = xs[32 + p0 + 1];
            float wav[4] = {wa.x, wa.y, wa.z, wa.w};
            float wbv[4] = {wb.x, wb.y, wb.z, wb.w};
            float bbv[4] = {b1r.x, b1r.y, b1r.z, b1r.w};
            u64 dzv[8];
#pragma unroll
            for (int ff = 0; ff < 4; ff++) {
                u64 wap = pack2(wav[ff], wav[ff]);
                u64 wbp = pack2(wbv[ff], wbv[ff]);
                u64 bbp = pack2(bbv[ff], bbv[ff]);
                u64 z0 = ffma2(xa0, wap, ffma2(xb0, wbp, bbp));
                u64 z1 = ffma2(xa1, wap, ffma2(xb1, wbp, bbp));
                u64 h0, d0, h1, d1;
                silu2(z0, h0, d0);  silu2(z1, h1, d1);
                dzv[2 * ff]     = fmul2(acc[2 * ff],     d0);
                dzv[2 * ff + 1] = fmul2(acc[2 * ff + 1], d1);
            }
            __syncthreads();
#pragma unroll
            for (int ff = 0; ff < 4; ff++) {
                ulonglong2 st; st.x = dzv[2 * ff]; st.y = dzv[2 * ff + 1];
                *reinterpret_cast<ulonglong2*>(&cur[f0 + ff][p0]) = st;
            }
        }
        __syncthreads();

        // ---- g = dz1 @ W1^T, clip, Langevin update ----
        {
            u64 gacc = 0ULL;
            const float* wrow = w1s + pd * 128 + part * 16;
            const u64 (*crow)[CPAD] = cur + part * 16;
#pragma unroll
            for (int jj = 0; jj < 16; jj++) {
                float w = wrow[jj];
                gacc = ffma2(crow[jj][pp], pack2(w, w), gacc);
            }
            gacc = fadd2(gacc, __shfl_down_sync(0xffffffffu, gacc, 4, 8));
            gacc = fadd2(gacc, __shfl_down_sync(0xffffffffu, gacc, 2, 8));
            gacc = fadd2(gacc, __shfl_down_sync(0xffffffffu, gacc, 1, 8));
            if (part == 0) {
                float2 g = unpack2(gacc);
                g.x = fminf(fmaxf(g.x, -0.03f), 0.03f);
                g.y = fminf(fmaxf(g.y, -0.03f), 0.03f);
                float2 xv = unpack2(xs[pd * 32 + pp]);
                float ax = xv.x + cn * nz0;  ax += eps * g.x;
                float ay = xv.y + cn * nz1;  ay += eps * g.y;
                ax = fminf(fmaxf(ax, -2.43f), 3.05f);
                ay = fminf(fmaxf(ay, -2.43f), 3.05f);
                xs[pd * 32 + pp] = pack2(ax, ay);
            }
        }
        __syncthreads();
    }

    // ---- write final x ----
    if (tid < 128) {
        int s = tid >> 1, d = tid & 1;
        float2 v = unpack2(xs[d * 32 + (s >> 1)]);
        out[(size_t)(s0 + s) * 2 + d] = (s & 1) ? v.y : v.x;
    }
}

extern "C" void kernel_launch(void* const* d_in, const int* in_sizes, int n_in,
                              void* d_out, int out_size) {
    const float* x0    = (const float*)d_in[0];
    const float* w1    = (const float*)d_in[1];
    const float* b1    = (const float*)d_in[2];
    const float* w2    = (const float*)d_in[3];
    const float* b2    = (const float*)d_in[4];
    const float* w3    = (const float*)d_in[5];
    const float* b3    = (const float*)d_in[6];
    const float* w4    = (const float*)d_in[7];
    const float* b4    = (const float*)d_in[8];
    const float* w5    = (const float*)d_in[9];
    const float* noise = (const float*)d_in[11];
    float* out = (float*)d_out;

    int nsamp = in_sizes[0] / 2;
    cudaFuncSetAttribute(ebm_mcmc_kernel,
                         cudaFuncAttributeMaxDynamicSharedMemorySize, SMEM_BYTES);
    int nblocks = nsamp / SB;
    ebm_mcmc_kernel<<<nblocks, NTHR, SMEM_BYTES>>>(
        x0, w1, b1, w2, b2, w3, b3, w4, b4, w5, noise, out, nsamp);
}